// round 11
// baseline (speedup 1.0000x reference)
#include <cuda_runtime.h>

#define N_NODES 200000
#define N_SUPER 20000
#define N_EDGES 640000
#define EMB 256
#define NBLK 196   // ceil(N_NODES / 1024) scan blocks

// ---------------- scratch (static device globals; no allocs) ----------------
__device__ __align__(16) float g_agg[(size_t)N_NODES * EMB];   // sum of x1[src] per dst
__device__ __align__(16) float g_proj[(size_t)N_SUPER * EMB];  // x1 rows of supernodes
__device__ __align__(16) int   g_rowmap[N_NODES];              // node -> supernode slot or -1
__device__ __align__(16) int   g_snode[N_SUPER];               // slot -> node id
__device__ __align__(16) int   g_cnt[N_NODES];                 // histogram, then scatter cursor
__device__ __align__(16) int   g_off[N_NODES + 1];             // CSR offsets (exclusive scan)
__device__ __align__(16) int   g_esrc[N_EDGES];                // encoded src: node id, or N_NODES+slot
__device__ int g_bsum[NBLK];
__device__ int g_bpre[NBLK];
__device__ int g_is64;

// ---------------- helpers ----------------
__device__ __forceinline__ int load_idx(const void* p, int i) {
    if (g_is64) return (int)((const long long*)p)[i];
    return ((const int*)p)[i];
}

__device__ __forceinline__ unsigned f2tf(float f) {
    unsigned u;
    asm("cvt.rna.tf32.f32 %0, %1;" : "=r"(u) : "f"(f));
    return u;
}

__device__ __forceinline__ void mma_tf32(float* c, const unsigned* a, const unsigned* b) {
    asm volatile("mma.sync.aligned.m16n8k8.row.col.f32.tf32.tf32.f32 "
                 "{%0,%1,%2,%3}, {%4,%5,%6,%7}, {%8,%9}, {%0,%1,%2,%3};"
                 : "+f"(c[0]), "+f"(c[1]), "+f"(c[2]), "+f"(c[3])
                 : "r"(a[0]), "r"(a[1]), "r"(a[2]), "r"(a[3]), "r"(b[0]), "r"(b[1]));
}

__device__ __forceinline__ const float4* row_ptr(int idx, const float* x) {
    return (idx < N_NODES) ? (const float4*)(x + (size_t)idx * EMB)
                           : (const float4*)(g_proj + (size_t)(idx - N_NODES) * EMB);
}

__device__ __forceinline__ void acc4(float4& a, const float4 v) {
    a.x += v.x; a.y += v.y; a.z += v.z; a.w += v.w;
}

// ---------------- dtype detection ----------------
__global__ void k_detect(const int* __restrict__ ei_words) {
    int all_zero = 1;
    for (int k = 0; k < 64; k++)
        if (ei_words[2 * k + 1] != 0) { all_zero = 0; break; }
    g_is64 = all_zero;
}

// ---------------- init ----------------
__global__ void k_init() {
    int i = blockIdx.x * blockDim.x + threadIdx.x;
    if (i < N_NODES) { g_rowmap[i] = -1; g_cnt[i] = 0; }
    if (i < N_SUPER) g_snode[i] = 0;
}

__global__ void k_set_rowmap(const void* __restrict__ sidx) {
    int s = blockIdx.x * blockDim.x + threadIdx.x;
    if (s < N_SUPER) {
        int v = load_idx(sidx, s);
        if (v >= 0 && v < N_NODES) { g_rowmap[v] = s; g_snode[s] = v; }
    }
}

// ---------------- CSR build: histogram -> scan -> scatter ----------------
__global__ void k_hist(const void* __restrict__ ei) {
    int e = blockIdx.x * blockDim.x + threadIdx.x;
    if (e >= N_EDGES) return;
    int dst = load_idx(ei, e);
    if (dst >= 0 && dst < N_NODES) atomicAdd(&g_cnt[dst], 1);
}

__global__ void k_scan1() {
    __shared__ int s[256];
    int b = blockIdx.x, t = threadIdx.x;
    int base = b * 1024 + t * 4;
    int v[4], sum = 0;
#pragma unroll
    for (int i = 0; i < 4; i++) {
        v[i] = (base + i < N_NODES) ? g_cnt[base + i] : 0;
        sum += v[i];
    }
    s[t] = sum;
    __syncthreads();
#pragma unroll
    for (int off = 1; off < 256; off <<= 1) {
        int add = (t >= off) ? s[t - off] : 0;
        __syncthreads();
        s[t] += add;
        __syncthreads();
    }
    int run = (t ? s[t - 1] : 0);
#pragma unroll
    for (int i = 0; i < 4; i++) {
        if (base + i < N_NODES) g_off[base + i] = run;
        run += v[i];
    }
    if (t == 255) g_bsum[b] = s[255];
}

__global__ void k_scan2() {
    __shared__ int s[256];
    int t = threadIdx.x;
    s[t] = (t < NBLK) ? g_bsum[t] : 0;
    __syncthreads();
#pragma unroll
    for (int off = 1; off < 256; off <<= 1) {
        int add = (t >= off) ? s[t - off] : 0;
        __syncthreads();
        s[t] += add;
        __syncthreads();
    }
    if (t < NBLK) g_bpre[t] = (t ? s[t - 1] : 0);
    if (t == 0) g_off[N_NODES] = s[NBLK - 1];
}

__global__ void k_scan3() {
    int i = blockIdx.x * blockDim.x + threadIdx.x;
    if (i < N_NODES) {
        g_off[i] += g_bpre[i >> 10];
        g_cnt[i] = 0;
    }
}

// scatter with supernode resolution baked in: store node id, or N_NODES+slot
__global__ void k_scatter(const void* __restrict__ ei) {
    int e = blockIdx.x * blockDim.x + threadIdx.x;
    if (e >= N_EDGES) return;
    int dst = load_idx(ei, e);
    int src = load_idx(ei, N_EDGES + e);
    if (dst < 0 || dst >= N_NODES || src < 0 || src >= N_NODES) return;
    int r = g_rowmap[src];
    int enc = (r >= 0) ? (N_NODES + r) : src;
    int pos = g_off[dst] + atomicAdd(&g_cnt[dst], 1);
    g_esrc[pos] = enc;
}

// ---------------- accumulate: 4 dst rows per warp in lockstep (high MLP) ----------
__global__ void __launch_bounds__(256) k_accum(const float* __restrict__ x) {
    int w  = blockIdx.x * 8 + (threadIdx.x >> 5);   // warp id, one warp = 4 rows
    int d0 = w * 4;
    if (d0 >= N_NODES) return;
    int lane = threadIdx.x & 31;

    int j0 = g_off[d0],     e0 = g_off[d0 + 1];
    int j1 = e0,            e1 = g_off[d0 + 2];
    int j2 = e1,            e2 = g_off[d0 + 3];
    int j3 = e2,            e3 = g_off[d0 + 4];

    float4 a00 = make_float4(0.f,0.f,0.f,0.f), a01 = a00;
    float4 a10 = a00, a11 = a00;
    float4 a20 = a00, a21 = a00;
    float4 a30 = a00, a31 = a00;

    while ((j0 < e0) | (j1 < e1) | (j2 < e2) | (j3 < e3)) {
        // warp-uniform predicates -> no divergence; up to 8 row-loads in flight
        const float4 *p0 = 0, *p1 = 0, *p2 = 0, *p3 = 0;
        if (j0 < e0) p0 = row_ptr(g_esrc[j0], x);
        if (j1 < e1) p1 = row_ptr(g_esrc[j1], x);
        if (j2 < e2) p2 = row_ptr(g_esrc[j2], x);
        if (j3 < e3) p3 = row_ptr(g_esrc[j3], x);
        if (p0) { float4 v0 = p0[lane], v1 = p0[lane + 32]; acc4(a00, v0); acc4(a01, v1); j0++; }
        if (p1) { float4 v0 = p1[lane], v1 = p1[lane + 32]; acc4(a10, v0); acc4(a11, v1); j1++; }
        if (p2) { float4 v0 = p2[lane], v1 = p2[lane + 32]; acc4(a20, v0); acc4(a21, v1); j2++; }
        if (p3) { float4 v0 = p3[lane], v1 = p3[lane + 32]; acc4(a30, v0); acc4(a31, v1); j3++; }
    }

    float4* r0 = (float4*)(g_agg + (size_t)(d0 + 0) * EMB);
    float4* r1 = (float4*)(g_agg + (size_t)(d0 + 1) * EMB);
    float4* r2 = (float4*)(g_agg + (size_t)(d0 + 2) * EMB);
    float4* r3 = (float4*)(g_agg + (size_t)(d0 + 3) * EMB);
    r0[lane] = a00; r0[lane + 32] = a01;
    r1[lane] = a10; r1[lane + 32] = a11;
    r2[lane] = a20; r2[lane + 32] = a21;
    r3[lane] = a30; r3[lane + 32] = a31;
}

// ---------------- tf32 tensor-core GEMM:  C = A @ W^T (+ epilogue) ----------------
// Block tile 64(M) x 256(N); 8 warps as 2(M) x 4(N); warp tile 32 x 64.
// mode 0 (proj):  C = acc + bias + x[g_snode[row]]
// mode 1 (final): C = acc + bias*deg + (r>=0 ? projx[r] : x[row])
#define BM 64
#define BN 256
#define BK 32
#define PAD 36

__global__ void __launch_bounds__(256, 2)
k_gemm_tf32(const float* __restrict__ A, const float* __restrict__ W,
            const float* __restrict__ bias, float* __restrict__ C, int M,
            const float* __restrict__ x, int final_mode)
{
    __shared__ unsigned As[BM * PAD];   // [m][k]
    __shared__ unsigned Bs[BN * PAD];   // [n][k]

    const int tid  = threadIdx.x;
    const int warp = tid >> 5, lane = tid & 31;
    const int wm   = warp >> 2, wn = warp & 3;     // 2 x 4 warp grid
    const int gid  = lane >> 2, tg = lane & 3;
    const int row0 = blockIdx.x * BM;

    float c[2][8][4];
#pragma unroll
    for (int mt = 0; mt < 2; mt++)
#pragma unroll
        for (int nt = 0; nt < 8; nt++)
#pragma unroll
            for (int q = 0; q < 4; q++) c[mt][nt][q] = 0.f;

    for (int k0 = 0; k0 < EMB; k0 += BK) {
#pragma unroll
        for (int t = 0; t < 2; t++) {
            int f = tid + t * 256;
            int m = f >> 3, kq = f & 7;
            int row = row0 + m;
            float4 v = make_float4(0.f, 0.f, 0.f, 0.f);
            if (row < M) v = *(const float4*)(A + (size_t)row * EMB + k0 + kq * 4);
            unsigned* p = &As[m * PAD + kq * 4];
            p[0] = f2tf(v.x); p[1] = f2tf(v.y); p[2] = f2tf(v.z); p[3] = f2tf(v.w);
        }
#pragma unroll
        for (int t = 0; t < 8; t++) {
            int f = tid + t * 256;
            int n = f >> 3, kq = f & 7;
            float4 v = *(const float4*)(W + (size_t)n * EMB + k0 + kq * 4);
            unsigned* p = &Bs[n * PAD + kq * 4];
            p[0] = f2tf(v.x); p[1] = f2tf(v.y); p[2] = f2tf(v.z); p[3] = f2tf(v.w);
        }
        __syncthreads();

#pragma unroll
        for (int ks = 0; ks < BK; ks += 8) {
            unsigned a[2][4], b[8][2];
#pragma unroll
            for (int mt = 0; mt < 2; mt++) {
                int mb = wm * 32 + mt * 16 + gid;
                a[mt][0] = As[mb * PAD + ks + tg];
                a[mt][1] = As[(mb + 8) * PAD + ks + tg];
                a[mt][2] = As[mb * PAD + ks + tg + 4];
                a[mt][3] = As[(mb + 8) * PAD + ks + tg + 4];
            }
#pragma unroll
            for (int nt = 0; nt < 8; nt++) {
                int nb = wn * 64 + nt * 8 + gid;
                b[nt][0] = Bs[nb * PAD + ks + tg];
                b[nt][1] = Bs[nb * PAD + ks + tg + 4];
            }
#pragma unroll
            for (int mt = 0; mt < 2; mt++)
#pragma unroll
                for (int nt = 0; nt < 8; nt++)
                    mma_tf32(c[mt][nt], a[mt], b[nt]);
        }
        __syncthreads();
    }

    // ---------------- epilogue ----------------
#pragma unroll
    for (int mt = 0; mt < 2; mt++) {
#pragma unroll
        for (int half = 0; half < 2; half++) {
            int row = row0 + wm * 32 + mt * 16 + gid + half * 8;
            if (row >= M) continue;
            float dg = 1.f;
            const float* addrow;
            if (final_mode) {
                dg = (float)(g_off[row + 1] - g_off[row]);   // in-degree
                int r = g_rowmap[row];
                addrow = (r >= 0) ? (g_proj + (size_t)r * EMB)
                                  : (x + (size_t)row * EMB);
            } else {
                addrow = x + (size_t)g_snode[row] * EMB;     // projx = proj + x[snode]
            }
#pragma unroll
            for (int nt = 0; nt < 8; nt++) {
                int col = wn * 64 + nt * 8 + 2 * tg;
                float v0 = c[mt][nt][half * 2 + 0] + bias[col]     * dg;
                float v1 = c[mt][nt][half * 2 + 1] + bias[col + 1] * dg;
                float2 av = *(const float2*)(addrow + col);
                v0 += av.x; v1 += av.y;
                *(float2*)(C + (size_t)row * EMB + col) = make_float2(v0, v1);
            }
        }
    }
}

// ---------------- launch ----------------
extern "C" void kernel_launch(void* const* d_in, const int* in_sizes, int n_in,
                              void* d_out, int out_size) {
    const float *x = nullptr, *snx = nullptr;
    const float *W1 = nullptr, *b1 = nullptr, *W2 = nullptr, *b2 = nullptr;
    const void  *ei = nullptr, *sidx = nullptr;

    for (int i = 0; i < n_in; i++) {
        int s = in_sizes[i];
        if      (s == N_NODES * EMB)  x    = (const float*)d_in[i];
        else if (s == N_SUPER * EMB)  snx  = (const float*)d_in[i];
        else if (s == 2 * N_EDGES)    ei   = d_in[i];
        else if (s == N_SUPER)        sidx = d_in[i];
        else if (s == N_NODES)        { /* graph_batch, unused */ }
        else if (s == EMB * EMB) { if (!W1) W1 = (const float*)d_in[i]; else W2 = (const float*)d_in[i]; }
        else if (s == EMB)       { if (!b1) b1 = (const float*)d_in[i]; else b2 = (const float*)d_in[i]; }
    }
    float* out = (float*)d_out;

    void *p_agg, *p_proj;
    cudaGetSymbolAddress(&p_agg,  g_agg);
    cudaGetSymbolAddress(&p_proj, g_proj);

    // detection + init + CSR build
    k_detect<<<1, 1>>>((const int*)ei);
    k_init<<<(N_NODES + 255) / 256, 256>>>();
    k_set_rowmap<<<(N_SUPER + 255) / 256, 256>>>(sidx);
    k_hist<<<(N_EDGES + 255) / 256, 256>>>(ei);
    k_scan1<<<NBLK, 256>>>();
    k_scan2<<<1, 256>>>();
    k_scan3<<<(N_NODES + 255) / 256, 256>>>();
    k_scatter<<<(N_EDGES + 255) / 256, 256>>>(ei);

    // step 1: projx = x[sidx] + snx @ W1^T + b1  (supernode x1 rows)
    k_gemm_tf32<<<(N_SUPER + BM - 1) / BM, 256>>>(snx, W1, b1, (float*)p_proj,
                                                  N_SUPER, x, 0);

    // step 2a: agg — 4 rows per warp, lockstep gather
    k_accum<<<(N_NODES / 4 + 7) / 8, 256>>>(x);

    // step 2b: out = x1 + agg @ W2^T + deg * b2
    k_gemm_tf32<<<(N_NODES + BM - 1) / BM, 256>>>((const float*)p_agg, W2, b2, out,
                                                  N_NODES, x, 1);
}

// round 12
// speedup vs baseline: 1.0621x; 1.0621x over previous
#include <cuda_runtime.h>

#define N_NODES 200000
#define N_SUPER 20000
#define N_EDGES 640000
#define EMB 256
#define NBLK 196   // ceil(N_NODES / 1024) scan blocks

// ---------------- scratch (static device globals; no allocs) ----------------
__device__ __align__(16) float    g_agg[(size_t)N_NODES * EMB];   // tf32-rounded agg rows
__device__ __align__(16) float    g_proj[(size_t)N_SUPER * EMB];  // x1 rows of supernodes
__device__ __align__(16) unsigned g_W2t[EMB * EMB];               // W2 pre-converted to tf32
__device__ __align__(16) int      g_rowmap[N_NODES];
__device__ __align__(16) int      g_snode[N_SUPER];
__device__ __align__(16) int      g_cnt[N_NODES];
__device__ __align__(16) int      g_off[N_NODES + 1];
__device__ __align__(16) int      g_esrc[N_EDGES];                // node id, or N_NODES+slot
__device__ int g_bsum[NBLK];
__device__ int g_bpre[NBLK];
__device__ int g_is64;

// ---------------- helpers ----------------
__device__ __forceinline__ int load_idx(const void* p, int i) {
    if (g_is64) return (int)((const long long*)p)[i];
    return ((const int*)p)[i];
}

__device__ __forceinline__ unsigned f2tf(float f) {
    unsigned u;
    asm("cvt.rna.tf32.f32 %0, %1;" : "=r"(u) : "f"(f));
    return u;
}

__device__ __forceinline__ void mma_tf32(float* c, const unsigned* a, const unsigned* b) {
    asm volatile("mma.sync.aligned.m16n8k8.row.col.f32.tf32.tf32.f32 "
                 "{%0,%1,%2,%3}, {%4,%5,%6,%7}, {%8,%9}, {%0,%1,%2,%3};"
                 : "+f"(c[0]), "+f"(c[1]), "+f"(c[2]), "+f"(c[3])
                 : "r"(a[0]), "r"(a[1]), "r"(a[2]), "r"(a[3]), "r"(b[0]), "r"(b[1]));
}

__device__ __forceinline__ const float4* row_ptr(int idx, const float* x) {
    return (idx < N_NODES) ? (const float4*)(x + (size_t)idx * EMB)
                           : (const float4*)(g_proj + (size_t)(idx - N_NODES) * EMB);
}

__device__ __forceinline__ void acc4(float4& a, const float4 v) {
    a.x += v.x; a.y += v.y; a.z += v.z; a.w += v.w;
}

// ---------------- init (includes int64 detection in thread 0) ----------------
__global__ void k_init(const int* __restrict__ ei_words) {
    int i = blockIdx.x * blockDim.x + threadIdx.x;
    if (i == 0) {
        int all_zero = 1;
        for (int k = 0; k < 64; k++)
            if (ei_words[2 * k + 1] != 0) { all_zero = 0; break; }
        g_is64 = all_zero;
    }
    if (i < N_NODES) { g_rowmap[i] = -1; g_cnt[i] = 0; }
    if (i < N_SUPER) g_snode[i] = 0;
}

__global__ void k_set_rowmap(const void* __restrict__ sidx) {
    int s = blockIdx.x * blockDim.x + threadIdx.x;
    if (s < N_SUPER) {
        int v = load_idx(sidx, s);
        if (v >= 0 && v < N_NODES) { g_rowmap[v] = s; g_snode[s] = v; }
    }
}

// pre-convert W2 to tf32
__global__ void k_cvtW(const float* __restrict__ W2) {
    int i = blockIdx.x * blockDim.x + threadIdx.x;
    if (i < EMB * EMB) g_W2t[i] = f2tf(W2[i]);
}

// ---------------- CSR build: histogram -> scan -> scatter ----------------
__global__ void k_hist(const void* __restrict__ ei) {
    int e = blockIdx.x * blockDim.x + threadIdx.x;
    if (e >= N_EDGES) return;
    int dst = load_idx(ei, e);
    if (dst >= 0 && dst < N_NODES) atomicAdd(&g_cnt[dst], 1);
}

__global__ void k_scan1() {
    __shared__ int s[256];
    int b = blockIdx.x, t = threadIdx.x;
    int base = b * 1024 + t * 4;
    int v[4], sum = 0;
#pragma unroll
    for (int i = 0; i < 4; i++) {
        v[i] = (base + i < N_NODES) ? g_cnt[base + i] : 0;
        sum += v[i];
    }
    s[t] = sum;
    __syncthreads();
#pragma unroll
    for (int off = 1; off < 256; off <<= 1) {
        int add = (t >= off) ? s[t - off] : 0;
        __syncthreads();
        s[t] += add;
        __syncthreads();
    }
    int run = (t ? s[t - 1] : 0);
#pragma unroll
    for (int i = 0; i < 4; i++) {
        if (base + i < N_NODES) g_off[base + i] = run;
        run += v[i];
    }
    if (t == 255) g_bsum[b] = s[255];
}

__global__ void k_scan2() {
    __shared__ int s[256];
    int t = threadIdx.x;
    s[t] = (t < NBLK) ? g_bsum[t] : 0;
    __syncthreads();
#pragma unroll
    for (int off = 1; off < 256; off <<= 1) {
        int add = (t >= off) ? s[t - off] : 0;
        __syncthreads();
        s[t] += add;
        __syncthreads();
    }
    if (t < NBLK) g_bpre[t] = (t ? s[t - 1] : 0);
    if (t == 0) g_off[N_NODES] = s[NBLK - 1];
}

__global__ void k_scan3() {
    int i = blockIdx.x * blockDim.x + threadIdx.x;
    if (i < N_NODES) {
        g_off[i] += g_bpre[i >> 10];
        g_cnt[i] = 0;
    }
}

__global__ void k_scatter(const void* __restrict__ ei) {
    int e = blockIdx.x * blockDim.x + threadIdx.x;
    if (e >= N_EDGES) return;
    int dst = load_idx(ei, e);
    int src = load_idx(ei, N_EDGES + e);
    if (dst < 0 || dst >= N_NODES || src < 0 || src >= N_NODES) return;
    int r = g_rowmap[src];
    int enc = (r >= 0) ? (N_NODES + r) : src;
    int pos = g_off[dst] + atomicAdd(&g_cnt[dst], 1);
    g_esrc[pos] = enc;
}

// ---------------- accumulate (R9 form): 1 row/warp, MLP-8; stores tf32 bits ------
__global__ void __launch_bounds__(256) k_accum(const float* __restrict__ x) {
    int d = blockIdx.x * 8 + (threadIdx.x >> 5);
    if (d >= N_NODES) return;
    int lane = threadIdx.x & 31;
    int j   = g_off[d];
    int end = g_off[d + 1];
    float4 a0 = make_float4(0.f, 0.f, 0.f, 0.f);
    float4 a1 = make_float4(0.f, 0.f, 0.f, 0.f);

    for (; j + 4 <= end; j += 4) {
        int i0 = g_esrc[j], i1 = g_esrc[j + 1], i2 = g_esrc[j + 2], i3 = g_esrc[j + 3];
        const float4* p0 = row_ptr(i0, x);
        const float4* p1 = row_ptr(i1, x);
        const float4* p2 = row_ptr(i2, x);
        const float4* p3 = row_ptr(i3, x);
        float4 v00 = p0[lane], v01 = p0[lane + 32];
        float4 v10 = p1[lane], v11 = p1[lane + 32];
        float4 v20 = p2[lane], v21 = p2[lane + 32];
        float4 v30 = p3[lane], v31 = p3[lane + 32];
        acc4(a0, v00); acc4(a1, v01);
        acc4(a0, v10); acc4(a1, v11);
        acc4(a0, v20); acc4(a1, v21);
        acc4(a0, v30); acc4(a1, v31);
    }
    for (; j < end; j++) {
        const float4* p = row_ptr(g_esrc[j], x);
        acc4(a0, p[lane]); acc4(a1, p[lane + 32]);
    }
    float4* dr = (float4*)(g_agg + (size_t)d * EMB);
    dr[lane] = make_float4(__uint_as_float(f2tf(a0.x)), __uint_as_float(f2tf(a0.y)),
                           __uint_as_float(f2tf(a0.z)), __uint_as_float(f2tf(a0.w)));
    dr[lane + 32] = make_float4(__uint_as_float(f2tf(a1.x)), __uint_as_float(f2tf(a1.y)),
                                __uint_as_float(f2tf(a1.z)), __uint_as_float(f2tf(a1.w)));
}

// ---------------- gemm1 (small): C = A @ W^T + bias + x[g_snode[row]] ----------------
#define BM 64
#define BN 256
#define BK 32
#define PAD 36

__global__ void __launch_bounds__(256, 2)
k_gemm1(const float* __restrict__ A, const float* __restrict__ W,
        const float* __restrict__ bias, float* __restrict__ C, int M,
        const float* __restrict__ x)
{
    __shared__ unsigned As[BM * PAD];
    __shared__ unsigned Bs[BN * PAD];

    const int tid  = threadIdx.x;
    const int warp = tid >> 5, lane = tid & 31;
    const int wm   = warp >> 2, wn = warp & 3;
    const int gid  = lane >> 2, tg = lane & 3;
    const int row0 = blockIdx.x * BM;

    float c[2][8][4];
#pragma unroll
    for (int mt = 0; mt < 2; mt++)
#pragma unroll
        for (int nt = 0; nt < 8; nt++)
#pragma unroll
            for (int q = 0; q < 4; q++) c[mt][nt][q] = 0.f;

    for (int k0 = 0; k0 < EMB; k0 += BK) {
#pragma unroll
        for (int t = 0; t < 2; t++) {
            int f = tid + t * 256;
            int m = f >> 3, kq = f & 7;
            int row = row0 + m;
            float4 v = make_float4(0.f, 0.f, 0.f, 0.f);
            if (row < M) v = *(const float4*)(A + (size_t)row * EMB + k0 + kq * 4);
            unsigned* p = &As[m * PAD + kq * 4];
            p[0] = f2tf(v.x); p[1] = f2tf(v.y); p[2] = f2tf(v.z); p[3] = f2tf(v.w);
        }
#pragma unroll
        for (int t = 0; t < 8; t++) {
            int f = tid + t * 256;
            int n = f >> 3, kq = f & 7;
            float4 v = *(const float4*)(W + (size_t)n * EMB + k0 + kq * 4);
            unsigned* p = &Bs[n * PAD + kq * 4];
            p[0] = f2tf(v.x); p[1] = f2tf(v.y); p[2] = f2tf(v.z); p[3] = f2tf(v.w);
        }
        __syncthreads();

#pragma unroll
        for (int ks = 0; ks < BK; ks += 8) {
            unsigned a[2][4], b[8][2];
#pragma unroll
            for (int mt = 0; mt < 2; mt++) {
                int mb = wm * 32 + mt * 16 + gid;
                a[mt][0] = As[mb * PAD + ks + tg];
                a[mt][1] = As[(mb + 8) * PAD + ks + tg];
                a[mt][2] = As[mb * PAD + ks + tg + 4];
                a[mt][3] = As[(mb + 8) * PAD + ks + tg + 4];
            }
#pragma unroll
            for (int nt = 0; nt < 8; nt++) {
                int nb = wn * 64 + nt * 8 + gid;
                b[nt][0] = Bs[nb * PAD + ks + tg];
                b[nt][1] = Bs[nb * PAD + ks + tg + 4];
            }
#pragma unroll
            for (int mt = 0; mt < 2; mt++)
#pragma unroll
                for (int nt = 0; nt < 8; nt++)
                    mma_tf32(c[mt][nt], a[mt], b[nt]);
        }
        __syncthreads();
    }

#pragma unroll
    for (int mt = 0; mt < 2; mt++) {
#pragma unroll
        for (int half = 0; half < 2; half++) {
            int row = row0 + wm * 32 + mt * 16 + gid + half * 8;
            if (row >= M) continue;
            const float* addrow = x + (size_t)g_snode[row] * EMB;
#pragma unroll
            for (int nt = 0; nt < 8; nt++) {
                int col = wn * 64 + nt * 8 + 2 * tg;
                float v0 = c[mt][nt][half * 2 + 0] + bias[col];
                float v1 = c[mt][nt][half * 2 + 1] + bias[col + 1];
                float2 av = *(const float2*)(addrow + col);
                v0 += av.x; v1 += av.y;
                *(float2*)(C + (size_t)row * EMB + col) = make_float2(v0, v1);
            }
        }
    }
}

// ---------------- gemm2 (final): cp.async double-buffered, pre-converted tf32 -------
// BM=128 x BN=256, 512 threads (4x4 warps), BK=32, 2 stages.
#define G2_BM   128
#define G2_PAD  36
#define G2_STAGE (G2_BM * G2_PAD + 256 * G2_PAD)   // 13824 words
#define G2_SMEM  (2 * G2_STAGE * 4)                // 110,592 bytes

__device__ __forceinline__ void cpa16(unsigned daddr, const void* src, int sz) {
    asm volatile("cp.async.cg.shared.global [%0], [%1], 16, %2;"
                 :: "r"(daddr), "l"(src), "r"(sz));
}

__global__ void __launch_bounds__(512, 1)
k_gemm2(const float* __restrict__ A, const float* __restrict__ bias,
        float* __restrict__ out, const float* __restrict__ x)
{
    extern __shared__ unsigned sm2[];
    const int tid  = threadIdx.x;
    const int warp = tid >> 5, lane = tid & 31;
    const int wm   = warp >> 2, wn = warp & 3;     // 4 x 4 warp grid
    const int gid  = lane >> 2, tg = lane & 3;
    const int row0 = blockIdx.x * G2_BM;

    float c[2][8][4];
#pragma unroll
    for (int mt = 0; mt < 2; mt++)
#pragma unroll
        for (int nt = 0; nt < 8; nt++)
#pragma unroll
            for (int q = 0; q < 4; q++) c[mt][nt][q] = 0.f;

    // stage loader: A tile 128x32 (1024 chunks), B tile 256x32 (2048 chunks)
    auto load_stage = [&](int k0, int buf) {
        unsigned* As = sm2 + buf * G2_STAGE;
        unsigned* Bs = As + G2_BM * G2_PAD;
#pragma unroll
        for (int t = 0; t < 2; t++) {
            int ch = tid + t * 512;
            int m = ch >> 3, kq = ch & 7;
            int row = row0 + m;
            int ok = row < N_NODES;
            const float* src = A + (size_t)(ok ? row : 0) * EMB + k0 + kq * 4;
            cpa16((unsigned)__cvta_generic_to_shared(&As[m * G2_PAD + kq * 4]),
                  src, ok ? 16 : 0);
        }
#pragma unroll
        for (int t = 0; t < 4; t++) {
            int ch = tid + t * 512;
            int n = ch >> 3, kq = ch & 7;
            cpa16((unsigned)__cvta_generic_to_shared(&Bs[n * G2_PAD + kq * 4]),
                  g_W2t + n * EMB + k0 + kq * 4, 16);
        }
        asm volatile("cp.async.commit_group;" ::: "memory");
    };

    load_stage(0, 0);

    for (int s = 0; s < 8; s++) {
        if (s < 7) {
            load_stage((s + 1) * BK, (s + 1) & 1);
            asm volatile("cp.async.wait_group 1;" ::: "memory");
        } else {
            asm volatile("cp.async.wait_group 0;" ::: "memory");
        }
        __syncthreads();

        const unsigned* As = sm2 + (s & 1) * G2_STAGE;
        const unsigned* Bs = As + G2_BM * G2_PAD;

#pragma unroll
        for (int ks = 0; ks < BK; ks += 8) {
            unsigned a[2][4], b[8][2];
#pragma unroll
            for (int mt = 0; mt < 2; mt++) {
                int mb = wm * 32 + mt * 16 + gid;
                a[mt][0] = As[mb * G2_PAD + ks + tg];
                a[mt][1] = As[(mb + 8) * G2_PAD + ks + tg];
                a[mt][2] = As[mb * G2_PAD + ks + tg + 4];
                a[mt][3] = As[(mb + 8) * G2_PAD + ks + tg + 4];
            }
#pragma unroll
            for (int nt = 0; nt < 8; nt++) {
                int nb = wn * 64 + nt * 8 + gid;
                b[nt][0] = Bs[nb * G2_PAD + ks + tg];
                b[nt][1] = Bs[nb * G2_PAD + ks + tg + 4];
            }
#pragma unroll
            for (int mt = 0; mt < 2; mt++)
#pragma unroll
                for (int nt = 0; nt < 8; nt++)
                    mma_tf32(c[mt][nt], a[mt], b[nt]);
        }
        __syncthreads();
    }

    // epilogue: out = acc + b2*deg + x1[row]
#pragma unroll
    for (int mt = 0; mt < 2; mt++) {
#pragma unroll
        for (int half = 0; half < 2; half++) {
            int row = row0 + wm * 32 + mt * 16 + gid + half * 8;
            if (row >= N_NODES) continue;
            float dg = (float)(g_off[row + 1] - g_off[row]);
            int r = g_rowmap[row];
            const float* addrow = (r >= 0) ? (g_proj + (size_t)r * EMB)
                                           : (x + (size_t)row * EMB);
#pragma unroll
            for (int nt = 0; nt < 8; nt++) {
                int col = wn * 64 + nt * 8 + 2 * tg;
                float v0 = c[mt][nt][half * 2 + 0] + bias[col]     * dg;
                float v1 = c[mt][nt][half * 2 + 1] + bias[col + 1] * dg;
                float2 av = *(const float2*)(addrow + col);
                v0 += av.x; v1 += av.y;
                *(float2*)(out + (size_t)row * EMB + col) = make_float2(v0, v1);
            }
        }
    }
}

// ---------------- launch ----------------
extern "C" void kernel_launch(void* const* d_in, const int* in_sizes, int n_in,
                              void* d_out, int out_size) {
    const float *x = nullptr, *snx = nullptr;
    const float *W1 = nullptr, *b1 = nullptr, *W2 = nullptr, *b2 = nullptr;
    const void  *ei = nullptr, *sidx = nullptr;

    for (int i = 0; i < n_in; i++) {
        int s = in_sizes[i];
        if      (s == N_NODES * EMB)  x    = (const float*)d_in[i];
        else if (s == N_SUPER * EMB)  snx  = (const float*)d_in[i];
        else if (s == 2 * N_EDGES)    ei   = d_in[i];
        else if (s == N_SUPER)        sidx = d_in[i];
        else if (s == N_NODES)        { /* graph_batch, unused */ }
        else if (s == EMB * EMB) { if (!W1) W1 = (const float*)d_in[i]; else W2 = (const float*)d_in[i]; }
        else if (s == EMB)       { if (!b1) b1 = (const float*)d_in[i]; else b2 = (const float*)d_in[i]; }
    }
    float* out = (float*)d_out;

    void *p_agg, *p_proj;
    cudaGetSymbolAddress(&p_agg,  g_agg);
    cudaGetSymbolAddress(&p_proj, g_proj);

    cudaFuncSetAttribute(k_gemm2, cudaFuncAttributeMaxDynamicSharedMemorySize, G2_SMEM);

    // init (with dtype detect) + CSR build
    k_init<<<(N_NODES + 255) / 256, 256>>>((const int*)ei);
    k_set_rowmap<<<(N_SUPER + 255) / 256, 256>>>(sidx);
    k_cvtW<<<(EMB * EMB + 255) / 256, 256>>>(W2);
    k_hist<<<(N_EDGES + 255) / 256, 256>>>(ei);
    k_scan1<<<NBLK, 256>>>();
    k_scan2<<<1, 256>>>();
    k_scan3<<<(N_NODES + 255) / 256, 256>>>();
    k_scatter<<<(N_EDGES + 255) / 256, 256>>>(ei);

    // step 1: projx = x[sidx] + snx @ W1^T + b1
    k_gemm1<<<(N_SUPER + BM - 1) / BM, 256>>>(snx, W1, b1, (float*)p_proj, N_SUPER, x);

    // step 2a: agg rows (tf32-rounded)
    k_accum<<<(N_NODES + 7) / 8, 256>>>(x);

    // step 2b: out = x1 + agg @ W2^T + deg * b2   (cp.async pipelined)
    k_gemm2<<<(N_NODES + G2_BM - 1) / G2_BM, 512, G2_SMEM>>>((const float*)p_agg, b2, out, x);
}

// round 13
// speedup vs baseline: 1.2526x; 1.1793x over previous
#include <cuda_runtime.h>
#include <cuda_fp16.h>

#define N_NODES 200000
#define N_SUPER 20000
#define N_EDGES 640000
#define EMB 256
#define NBLK 196   // ceil(N_NODES / 1024) scan blocks

// ---------------- scratch (static device globals; no allocs) ----------------
__device__ __align__(16) __half   g_xh[(size_t)N_NODES * EMB];    // fp16 copy of x
__device__ __align__(16) __half   g_aggh[(size_t)N_NODES * EMB];  // fp16 agg rows
__device__ __align__(16) __half   g_projh[(size_t)N_SUPER * EMB]; // fp16 supernode x1 rows
__device__ __align__(16) float    g_proj[(size_t)N_SUPER * EMB];  // fp32 supernode x1 rows
__device__ __align__(16) __half   g_W2h[EMB * EMB];               // W2 in fp16
__device__ __align__(16) int      g_rowmap[N_NODES];
__device__ __align__(16) int      g_snode[N_SUPER];
__device__ __align__(16) int      g_cnt[N_NODES];
__device__ __align__(16) int      g_off[N_NODES + 1];
__device__ __align__(16) int      g_esrc[N_EDGES];                // node id, or N_NODES+slot
__device__ int g_bsum[NBLK];
__device__ int g_bpre[NBLK];
__device__ int g_is64;

// ---------------- helpers ----------------
__device__ __forceinline__ int load_idx(const void* p, int i) {
    if (g_is64) return (int)((const long long*)p)[i];
    return ((const int*)p)[i];
}

__device__ __forceinline__ unsigned f2tf(float f) {
    unsigned u;
    asm("cvt.rna.tf32.f32 %0, %1;" : "=r"(u) : "f"(f));
    return u;
}

__device__ __forceinline__ void mma_tf32(float* c, const unsigned* a, const unsigned* b) {
    asm volatile("mma.sync.aligned.m16n8k8.row.col.f32.tf32.tf32.f32 "
                 "{%0,%1,%2,%3}, {%4,%5,%6,%7}, {%8,%9}, {%0,%1,%2,%3};"
                 : "+f"(c[0]), "+f"(c[1]), "+f"(c[2]), "+f"(c[3])
                 : "r"(a[0]), "r"(a[1]), "r"(a[2]), "r"(a[3]), "r"(b[0]), "r"(b[1]));
}

__device__ __forceinline__ void mma_f16(float* c, const unsigned* a, const unsigned* b) {
    asm volatile("mma.sync.aligned.m16n8k16.row.col.f32.f16.f16.f32 "
                 "{%0,%1,%2,%3}, {%4,%5,%6,%7}, {%8,%9}, {%0,%1,%2,%3};"
                 : "+f"(c[0]), "+f"(c[1]), "+f"(c[2]), "+f"(c[3])
                 : "r"(a[0]), "r"(a[1]), "r"(a[2]), "r"(a[3]), "r"(b[0]), "r"(b[1]));
}

// encoded src -> fp16 row base
__device__ __forceinline__ const uint4* row_ptr_h(int idx) {
    const __half* p = (idx < N_NODES) ? (g_xh + (size_t)idx * EMB)
                                      : (g_projh + (size_t)(idx - N_NODES) * EMB);
    return (const uint4*)p;
}

// accumulate 8 halves (uint4) into float a[8]
__device__ __forceinline__ void acc_h8(float* a, uint4 r) {
    float2 f0 = __half22float2(*(__half2*)&r.x);
    float2 f1 = __half22float2(*(__half2*)&r.y);
    float2 f2 = __half22float2(*(__half2*)&r.z);
    float2 f3 = __half22float2(*(__half2*)&r.w);
    a[0] += f0.x; a[1] += f0.y; a[2] += f1.x; a[3] += f1.y;
    a[4] += f2.x; a[5] += f2.y; a[6] += f3.x; a[7] += f3.y;
}

// ---------------- init (includes int64 detection in thread 0) ----------------
__global__ void k_init(const int* __restrict__ ei_words) {
    int i = blockIdx.x * blockDim.x + threadIdx.x;
    if (i == 0) {
        int all_zero = 1;
        for (int k = 0; k < 64; k++)
            if (ei_words[2 * k + 1] != 0) { all_zero = 0; break; }
        g_is64 = all_zero;
    }
    if (i < N_NODES) { g_rowmap[i] = -1; g_cnt[i] = 0; }
    if (i < N_SUPER) g_snode[i] = 0;
}

__global__ void k_set_rowmap(const void* __restrict__ sidx) {
    int s = blockIdx.x * blockDim.x + threadIdx.x;
    if (s < N_SUPER) {
        int v = load_idx(sidx, s);
        if (v >= 0 && v < N_NODES) { g_rowmap[v] = s; g_snode[s] = v; }
    }
}

__global__ void k_cvtW(const float* __restrict__ W2) {
    int i = blockIdx.x * blockDim.x + threadIdx.x;
    if (i < EMB * EMB) g_W2h[i] = __float2half_rn(W2[i]);
}

// x -> fp16 (8 floats per thread)
__global__ void k_prep(const float* __restrict__ x) {
    int i = blockIdx.x * blockDim.x + threadIdx.x;   // over N*EMB/8
    if (i >= N_NODES * (EMB / 8)) return;
    float4 v0 = ((const float4*)x)[2 * i];
    float4 v1 = ((const float4*)x)[2 * i + 1];
    __half2 h0 = __floats2half2_rn(v0.x, v0.y);
    __half2 h1 = __floats2half2_rn(v0.z, v0.w);
    __half2 h2 = __floats2half2_rn(v1.x, v1.y);
    __half2 h3 = __floats2half2_rn(v1.z, v1.w);
    uint4 o;
    o.x = *(unsigned*)&h0; o.y = *(unsigned*)&h1;
    o.z = *(unsigned*)&h2; o.w = *(unsigned*)&h3;
    ((uint4*)g_xh)[i] = o;
}

// ---------------- CSR build: histogram -> scan -> scatter ----------------
__global__ void k_hist(const void* __restrict__ ei) {
    int e = blockIdx.x * blockDim.x + threadIdx.x;
    if (e >= N_EDGES) return;
    int dst = load_idx(ei, e);
    if (dst >= 0 && dst < N_NODES) atomicAdd(&g_cnt[dst], 1);
}

__global__ void k_scan1() {
    __shared__ int s[256];
    int b = blockIdx.x, t = threadIdx.x;
    int base = b * 1024 + t * 4;
    int v[4], sum = 0;
#pragma unroll
    for (int i = 0; i < 4; i++) {
        v[i] = (base + i < N_NODES) ? g_cnt[base + i] : 0;
        sum += v[i];
    }
    s[t] = sum;
    __syncthreads();
#pragma unroll
    for (int off = 1; off < 256; off <<= 1) {
        int add = (t >= off) ? s[t - off] : 0;
        __syncthreads();
        s[t] += add;
        __syncthreads();
    }
    int run = (t ? s[t - 1] : 0);
#pragma unroll
    for (int i = 0; i < 4; i++) {
        if (base + i < N_NODES) g_off[base + i] = run;
        run += v[i];
    }
    if (t == 255) g_bsum[b] = s[255];
}

__global__ void k_scan2() {
    __shared__ int s[256];
    int t = threadIdx.x;
    s[t] = (t < NBLK) ? g_bsum[t] : 0;
    __syncthreads();
#pragma unroll
    for (int off = 1; off < 256; off <<= 1) {
        int add = (t >= off) ? s[t - off] : 0;
        __syncthreads();
        s[t] += add;
        __syncthreads();
    }
    if (t < NBLK) g_bpre[t] = (t ? s[t - 1] : 0);
    if (t == 0) g_off[N_NODES] = s[NBLK - 1];
}

__global__ void k_scan3() {
    int i = blockIdx.x * blockDim.x + threadIdx.x;
    if (i < N_NODES) {
        g_off[i] += g_bpre[i >> 10];
        g_cnt[i] = 0;
    }
}

__global__ void k_scatter(const void* __restrict__ ei) {
    int e = blockIdx.x * blockDim.x + threadIdx.x;
    if (e >= N_EDGES) return;
    int dst = load_idx(ei, e);
    int src = load_idx(ei, N_EDGES + e);
    if (dst < 0 || dst >= N_NODES || src < 0 || src >= N_NODES) return;
    int r = g_rowmap[src];
    int enc = (r >= 0) ? (N_NODES + r) : src;
    int pos = g_off[dst] + atomicAdd(&g_cnt[dst], 1);
    g_esrc[pos] = enc;
}

// ---------------- accumulate: fp16 gather (512B/row), fp32 acc, fp16 store --------
__global__ void __launch_bounds__(256) k_accum() {
    int d = blockIdx.x * 8 + (threadIdx.x >> 5);
    if (d >= N_NODES) return;
    int lane = threadIdx.x & 31;
    int j   = g_off[d];
    int end = g_off[d + 1];
    float a[8];
#pragma unroll
    for (int t = 0; t < 8; t++) a[t] = 0.f;

    for (; j + 4 <= end; j += 4) {
        const uint4* p0 = row_ptr_h(g_esrc[j]);
        const uint4* p1 = row_ptr_h(g_esrc[j + 1]);
        const uint4* p2 = row_ptr_h(g_esrc[j + 2]);
        const uint4* p3 = row_ptr_h(g_esrc[j + 3]);
        uint4 r0 = p0[lane], r1 = p1[lane], r2 = p2[lane], r3 = p3[lane];
        acc_h8(a, r0); acc_h8(a, r1); acc_h8(a, r2); acc_h8(a, r3);
    }
    for (; j < end; j++)
        acc_h8(a, row_ptr_h(g_esrc[j])[lane]);

    __half2 h0 = __floats2half2_rn(a[0], a[1]);
    __half2 h1 = __floats2half2_rn(a[2], a[3]);
    __half2 h2 = __floats2half2_rn(a[4], a[5]);
    __half2 h3 = __floats2half2_rn(a[6], a[7]);
    uint4 o;
    o.x = *(unsigned*)&h0; o.y = *(unsigned*)&h1;
    o.z = *(unsigned*)&h2; o.w = *(unsigned*)&h3;
    ((uint4*)(g_aggh + (size_t)d * EMB))[lane] = o;
}

// ---------------- gemm1 (small, tf32): C = A @ W1^T + b1 + x[snode]; also projh ----
#define BM 64
#define BN 256
#define BK 32
#define PAD 36

__global__ void __launch_bounds__(256, 2)
k_gemm1(const float* __restrict__ A, const float* __restrict__ W,
        const float* __restrict__ bias, float* __restrict__ C, int M,
        const float* __restrict__ x)
{
    __shared__ unsigned As[BM * PAD];
    __shared__ unsigned Bs[BN * PAD];

    const int tid  = threadIdx.x;
    const int warp = tid >> 5, lane = tid & 31;
    const int wm   = warp >> 2, wn = warp & 3;
    const int gid  = lane >> 2, tg = lane & 3;
    const int row0 = blockIdx.x * BM;

    float c[2][8][4];
#pragma unroll
    for (int mt = 0; mt < 2; mt++)
#pragma unroll
        for (int nt = 0; nt < 8; nt++)
#pragma unroll
            for (int q = 0; q < 4; q++) c[mt][nt][q] = 0.f;

    for (int k0 = 0; k0 < EMB; k0 += BK) {
#pragma unroll
        for (int t = 0; t < 2; t++) {
            int f = tid + t * 256;
            int m = f >> 3, kq = f & 7;
            int row = row0 + m;
            float4 v = make_float4(0.f, 0.f, 0.f, 0.f);
            if (row < M) v = *(const float4*)(A + (size_t)row * EMB + k0 + kq * 4);
            unsigned* p = &As[m * PAD + kq * 4];
            p[0] = f2tf(v.x); p[1] = f2tf(v.y); p[2] = f2tf(v.z); p[3] = f2tf(v.w);
        }
#pragma unroll
        for (int t = 0; t < 8; t++) {
            int f = tid + t * 256;
            int n = f >> 3, kq = f & 7;
            float4 v = *(const float4*)(W + (size_t)n * EMB + k0 + kq * 4);
            unsigned* p = &Bs[n * PAD + kq * 4];
            p[0] = f2tf(v.x); p[1] = f2tf(v.y); p[2] = f2tf(v.z); p[3] = f2tf(v.w);
        }
        __syncthreads();

#pragma unroll
        for (int ks = 0; ks < BK; ks += 8) {
            unsigned a[2][4], b[8][2];
#pragma unroll
            for (int mt = 0; mt < 2; mt++) {
                int mb = wm * 32 + mt * 16 + gid;
                a[mt][0] = As[mb * PAD + ks + tg];
                a[mt][1] = As[(mb + 8) * PAD + ks + tg];
                a[mt][2] = As[mb * PAD + ks + tg + 4];
                a[mt][3] = As[(mb + 8) * PAD + ks + tg + 4];
            }
#pragma unroll
            for (int nt = 0; nt < 8; nt++) {
                int nb = wn * 64 + nt * 8 + gid;
                b[nt][0] = Bs[nb * PAD + ks + tg];
                b[nt][1] = Bs[nb * PAD + ks + tg + 4];
            }
#pragma unroll
            for (int mt = 0; mt < 2; mt++)
#pragma unroll
                for (int nt = 0; nt < 8; nt++)
                    mma_tf32(c[mt][nt], a[mt], b[nt]);
        }
        __syncthreads();
    }

#pragma unroll
    for (int mt = 0; mt < 2; mt++) {
#pragma unroll
        for (int half = 0; half < 2; half++) {
            int row = row0 + wm * 32 + mt * 16 + gid + half * 8;
            if (row >= M) continue;
            const float* addrow = x + (size_t)g_snode[row] * EMB;
#pragma unroll
            for (int nt = 0; nt < 8; nt++) {
                int col = wn * 64 + nt * 8 + 2 * tg;
                float v0 = c[mt][nt][half * 2 + 0] + bias[col];
                float v1 = c[mt][nt][half * 2 + 1] + bias[col + 1];
                float2 av = *(const float2*)(addrow + col);
                v0 += av.x; v1 += av.y;
                *(float2*)(C + (size_t)row * EMB + col) = make_float2(v0, v1);
                *(__half2*)(g_projh + (size_t)row * EMB + col) = __floats2half2_rn(v0, v1);
            }
        }
    }
}

// ---------------- gemm2 (final, fp16 mma): cp.async double-buffered ----------------
// BM=128 x BN=256, 512 threads (4x4 warps), BK=32 halves, 2 stages.
#define G2_BM   128
#define AW      20                         // words per A row per stage (16 + 4 pad)
#define BW      20
#define G2_ASZ  (G2_BM * AW)               // 2560 words
#define G2_STAGE (G2_ASZ + 256 * BW)       // 7680 words
#define G2_SMEM  (2 * G2_STAGE * 4)        // 61440 bytes

__device__ __forceinline__ void cpa16(unsigned daddr, const void* src, int sz) {
    asm volatile("cp.async.cg.shared.global [%0], [%1], 16, %2;"
                 :: "r"(daddr), "l"(src), "r"(sz));
}

__global__ void __launch_bounds__(512, 1)
k_gemm2(const float* __restrict__ bias, float* __restrict__ out,
        const float* __restrict__ x)
{
    extern __shared__ unsigned sm2[];
    const int tid  = threadIdx.x;
    const int warp = tid >> 5, lane = tid & 31;
    const int wm   = warp >> 2, wn = warp & 3;     // 4 x 4 warp grid
    const int gid  = lane >> 2, tg = lane & 3;
    const int row0 = blockIdx.x * G2_BM;

    float c[2][8][4];
#pragma unroll
    for (int mt = 0; mt < 2; mt++)
#pragma unroll
        for (int nt = 0; nt < 8; nt++)
#pragma unroll
            for (int q = 0; q < 4; q++) c[mt][nt][q] = 0.f;

    // stage loader: A 128 rows x 32 halves (512 chunks), B 256 x 32 halves (1024 chunks)
    auto load_stage = [&](int k0, int buf) {   // k0 in halves
        unsigned* As = sm2 + buf * G2_STAGE;
        unsigned* Bs = As + G2_ASZ;
        {
            int m = tid >> 2, j = tid & 3;
            int row = row0 + m;
            int ok = row < N_NODES;
            const char* src = (const char*)g_aggh +
                              ((size_t)(ok ? row : 0) * EMB + k0) * 2 + j * 16;
            cpa16((unsigned)__cvta_generic_to_shared(&As[m * AW + j * 4]),
                  src, ok ? 16 : 0);
        }
#pragma unroll
        for (int t = 0; t < 2; t++) {
            int ch = tid + t * 512;
            int n = ch >> 2, j = ch & 3;
            const char* src = (const char*)g_W2h + ((size_t)n * EMB + k0) * 2 + j * 16;
            cpa16((unsigned)__cvta_generic_to_shared(&Bs[n * BW + j * 4]), src, 16);
        }
        asm volatile("cp.async.commit_group;" ::: "memory");
    };

    load_stage(0, 0);

    for (int s = 0; s < 8; s++) {
        if (s < 7) {
            load_stage((s + 1) * 32, (s + 1) & 1);
            asm volatile("cp.async.wait_group 1;" ::: "memory");
        } else {
            asm volatile("cp.async.wait_group 0;" ::: "memory");
        }
        __syncthreads();

        const unsigned* As = sm2 + (s & 1) * G2_STAGE;
        const unsigned* Bs = As + G2_ASZ;

#pragma unroll
        for (int kw = 0; kw < 16; kw += 8) {   // two K=16 mma steps per stage
            unsigned a[2][4], b[8][2];
#pragma unroll
            for (int mt = 0; mt < 2; mt++) {
                int mb = wm * 32 + mt * 16 + gid;
                a[mt][0] = As[mb * AW + kw + tg];
                a[mt][1] = As[(mb + 8) * AW + kw + tg];
                a[mt][2] = As[mb * AW + kw + tg + 4];
                a[mt][3] = As[(mb + 8) * AW + kw + tg + 4];
            }
#pragma unroll
            for (int nt = 0; nt < 8; nt++) {
                int nb = wn * 64 + nt * 8 + gid;
                b[nt][0] = Bs[nb * BW + kw + tg];
                b[nt][1] = Bs[nb * BW + kw + tg + 4];
            }
#pragma unroll
            for (int mt = 0; mt < 2; mt++)
#pragma unroll
                for (int nt = 0; nt < 8; nt++)
                    mma_f16(c[mt][nt], a[mt], b[nt]);
        }
        __syncthreads();
    }

    // epilogue: out = acc + b2*deg + x1[row]  (all fp32)
#pragma unroll
    for (int mt = 0; mt < 2; mt++) {
#pragma unroll
        for (int half = 0; half < 2; half++) {
            int row = row0 + wm * 32 + mt * 16 + gid + half * 8;
            if (row >= N_NODES) continue;
            float dg = (float)(g_off[row + 1] - g_off[row]);
            int r = g_rowmap[row];
            const float* addrow = (r >= 0) ? (g_proj + (size_t)r * EMB)
                                           : (x + (size_t)row * EMB);
#pragma unroll
            for (int nt = 0; nt < 8; nt++) {
                int col = wn * 64 + nt * 8 + 2 * tg;
                float v0 = c[mt][nt][half * 2 + 0] + bias[col]     * dg;
                float v1 = c[mt][nt][half * 2 + 1] + bias[col + 1] * dg;
                float2 av = *(const float2*)(addrow + col);
                v0 += av.x; v1 += av.y;
                *(float2*)(out + (size_t)row * EMB + col) = make_float2(v0, v1);
            }
        }
    }
}

// ---------------- launch ----------------
extern "C" void kernel_launch(void* const* d_in, const int* in_sizes, int n_in,
                              void* d_out, int out_size) {
    const float *x = nullptr, *snx = nullptr;
    const float *W1 = nullptr, *b1 = nullptr, *W2 = nullptr, *b2 = nullptr;
    const void  *ei = nullptr, *sidx = nullptr;

    for (int i = 0; i < n_in; i++) {
        int s = in_sizes[i];
        if      (s == N_NODES * EMB)  x    = (const float*)d_in[i];
        else if (s == N_SUPER * EMB)  snx  = (const float*)d_in[i];
        else if (s == 2 * N_EDGES)    ei   = d_in[i];
        else if (s == N_SUPER)        sidx = d_in[i];
        else if (s == N_NODES)        { /* graph_batch, unused */ }
        else if (s == EMB * EMB) { if (!W1) W1 = (const float*)d_in[i]; else W2 = (const float*)d_in[i]; }
        else if (s == EMB)       { if (!b1) b1 = (const float*)d_in[i]; else b2 = (const float*)d_in[i]; }
    }
    float* out = (float*)d_out;

    void* p_proj;
    cudaGetSymbolAddress(&p_proj, g_proj);

    cudaFuncSetAttribute(k_gemm2, cudaFuncAttributeMaxDynamicSharedMemorySize, G2_SMEM);

    // prep + CSR build (capture slot = 4th launch = k_prep)
    k_init<<<(N_NODES + 255) / 256, 256>>>((const int*)ei);
    k_set_rowmap<<<(N_SUPER + 255) / 256, 256>>>(sidx);
    k_cvtW<<<(EMB * EMB + 255) / 256, 256>>>(W2);
    k_prep<<<(N_NODES * (EMB / 8) + 255) / 256, 256>>>(x);
    k_hist<<<(N_EDGES + 255) / 256, 256>>>(ei);
    k_scan1<<<NBLK, 256>>>();
    k_scan2<<<1, 256>>>();
    k_scan3<<<(N_NODES + 255) / 256, 256>>>();
    k_scatter<<<(N_EDGES + 255) / 256, 256>>>(ei);

    // step 1: projx = x[sidx] + snx @ W1^T + b1  (fp32 + fp16 copies)
    k_gemm1<<<(N_SUPER + BM - 1) / BM, 256>>>(snx, W1, b1, (float*)p_proj, N_SUPER, x);

    // step 2a: agg rows (fp16 gather, fp32 accumulate, fp16 store)
    k_accum<<<(N_NODES + 7) / 8, 256>>>();

    // step 2b: out = x1 + agg @ W2^T + deg * b2   (fp16 mma, fp32 epilogue)
    k_gemm2<<<(N_NODES + G2_BM - 1) / G2_BM, 512, G2_SMEM>>>(b2, out, x);
}